// round 16
// baseline (speedup 1.0000x reference)
#include <cuda_runtime.h>
#include <cfloat>
#include <math.h>

#define Bn 64
#define Dn 256
#define Ln 4096
#define DKn 128
#define LN_EPS 1e-6f
#define EPS_CLIP 1e-10f

#define CH1 64                 // l-chunk per block
#define NCH (Ln / CH1)         // 64 chunks per batch

// ---------------- scratch (static device globals; no allocation) ----------------
__device__ float g_mu[Bn * Ln];
__device__ float g_rsig[Bn * Ln];
__device__ float g_PU[Bn * NCH * 3 * Dn];
__device__ float g_PR[Bn * NCH * 3 * Dn];
__device__ float g_Psmr[Bn * NCH];
__device__ float g_Ps22[Bn * NCH];
__device__ float g_Pml[Bn * NCH];
__device__ float g_Pse[Bn * NCH];
__device__ float g_Pa[Bn * NCH];
__device__ float g_Pm2[Bn * NCH];
__device__ float g_gp[Bn * Dn];
__device__ float g_corr[Bn * Dn];
__device__ float g_Cb[Bn], g_Gp[Bn];
__device__ unsigned int g_ctrU[Bn];   // zero-init; winner resets each run
__device__ unsigned int g_ctrR[Bn];

// ---------------- reduction helpers ----------------
__device__ __forceinline__ float warpSum(float v) {
#pragma unroll
    for (int o = 16; o; o >>= 1) v += __shfl_xor_sync(0xffffffffu, v, o);
    return v;
}
__device__ __forceinline__ float warpMax(float v) {
#pragma unroll
    for (int o = 16; o; o >>= 1) v = fmaxf(v, __shfl_xor_sync(0xffffffffu, v, o));
    return v;
}
__device__ __forceinline__ float bSum(float v) {
    __shared__ float sh[32];
    int lane = threadIdx.x & 31, w = threadIdx.x >> 5;
    int nw = (blockDim.x + 31) >> 5;
    v = warpSum(v);
    if (lane == 0) sh[w] = v;
    __syncthreads();
    if (w == 0) {
        float x = (lane < nw) ? sh[lane] : 0.0f;
        x = warpSum(x);
        if (lane == 0) sh[0] = x;
    }
    __syncthreads();
    float r = sh[0];
    __syncthreads();
    return r;
}

// ---------------- 1. LN stats + U-partials + (last block per batch) combineU + qp ----------------
// 256 threads, 4 blocks/SM: dg = t>>4 (0..15) covers 16 d-rows, lv = t&15 the 64-l chunk.
__global__ void __launch_bounds__(256, 4) k_pass1(const float* __restrict__ v,
                                                  const float* __restrict__ wk,
                                                  const float* __restrict__ wq,
                                                  const float* __restrict__ ln_g,
                                                  const float* __restrict__ ln_b) {
    __shared__ float s_mu[CH1], s_rs[CH1], s_mr[CH1], s_m2[CH1];
    __shared__ float sA[64 * 17];
    __shared__ float sQ[64 * 17];
    __shared__ unsigned int s_ticket;

    int t = threadIdx.x;                    // 256
    int b = blockIdx.x >> 6;                // NCH == 64
    int ch = blockIdx.x & 63;
    int l0 = ch * CH1;
    int bc = blockIdx.x;
    int dg = t >> 4;                        // 0..15
    int lv = t & 15;

    const float* vbase = v + (size_t)b * Dn * Ln + l0 + lv * 4;
    float cs0 = 0.f, cs1 = 0.f, cs2 = 0.f, cs3 = 0.f;
    float cq0 = 0.f, cq1 = 0.f, cq2 = 0.f, cq3 = 0.f;
#pragma unroll
    for (int it = 0; it < 16; it++) {
        int d = it * 16 + dg;
        float4 x = *reinterpret_cast<const float4*>(vbase + (size_t)d * Ln);
        cs0 += x.x; cs1 += x.y; cs2 += x.z; cs3 += x.w;
        cq0 = fmaf(x.x, x.x, cq0);
        cq1 = fmaf(x.y, x.y, cq1);
        cq2 = fmaf(x.z, x.z, cq2);
        cq3 = fmaf(x.w, x.w, cq3);
    }
    sA[(lv * 4 + 0) * 17 + dg] = cs0;
    sA[(lv * 4 + 1) * 17 + dg] = cs1;
    sA[(lv * 4 + 2) * 17 + dg] = cs2;
    sA[(lv * 4 + 3) * 17 + dg] = cs3;
    sQ[(lv * 4 + 0) * 17 + dg] = cq0;
    sQ[(lv * 4 + 1) * 17 + dg] = cq1;
    sQ[(lv * 4 + 2) * 17 + dg] = cq2;
    sQ[(lv * 4 + 3) * 17 + dg] = cq3;
    __syncthreads();

    if (t < CH1) {
        float ss = 0.f, qq = 0.f;
#pragma unroll
        for (int g = 0; g < 16; g++) {
            ss += sA[t * 17 + g];
            qq += sQ[t * 17 + g];
        }
        float mu = ss * (1.0f / Dn);
        float var = qq * (1.0f / Dn) - mu * mu;
        float rs = rsqrtf(var + LN_EPS);
        s_mu[t] = mu;
        s_rs[t] = rs;
        g_mu[b * Ln + l0 + t] = mu;
        g_rsig[b * Ln + l0 + t] = rs;
        float mr = mu * rs;
        s_mr[t] = mr;
        s_m2[t] = mr * mr;
    }
    __syncthreads();

    if (t < 32) {
        float a = s_mr[t] + s_mr[32 + t];
        a = warpSum(a);
        if (t == 0) g_Psmr[bc] = a;
    } else if (t < 64) {
        int u = t - 32;
        float a = s_m2[u] + s_m2[32 + u];
        a = warpSum(a);
        if (u == 0) g_Ps22[bc] = a;
    }

    float r0 = s_rs[lv * 4 + 0], r1 = s_rs[lv * 4 + 1], r2 = s_rs[lv * 4 + 2], r3 = s_rs[lv * 4 + 3];
    float am0 = s_mu[lv * 4 + 0] * r0 * r0;
    float am1 = s_mu[lv * 4 + 1] * r1 * r1;
    float am2 = s_mu[lv * 4 + 2] * r2 * r2;
    float am3 = s_mu[lv * 4 + 3] * r3 * r3;

    // Phase B: re-read v (L2-hot). Half-warp (16-lane) reduction per d-row.
#pragma unroll
    for (int it = 0; it < 16; it++) {
        int d = it * 16 + dg;
        float4 xx = *reinterpret_cast<const float4*>(vbase + (size_t)d * Ln);
        float xr0 = xx.x * r0, xr1 = xx.y * r1, xr2 = xx.z * r2, xr3 = xx.w * r3;
        float u1 = (xr0 + xr1) + (xr2 + xr3);
        float u2 = fmaf(xr0, xr0, fmaf(xr1, xr1, fmaf(xr2, xr2, xr3 * xr3)));
        float u3 = fmaf(xx.x, am0, fmaf(xx.y, am1, fmaf(xx.z, am2, xx.w * am3)));
#pragma unroll
        for (int o = 8; o; o >>= 1) {
            u1 += __shfl_down_sync(0xffffffffu, u1, o);
            u2 += __shfl_down_sync(0xffffffffu, u2, o);
            u3 += __shfl_down_sync(0xffffffffu, u3, o);
        }
        if (lv == 0) {
            g_PU[(bc * 3 + 0) * Dn + d] = u1;
            g_PU[(bc * 3 + 1) * Dn + d] = u2;
            g_PU[(bc * 3 + 2) * Dn + d] = u3;
        }
    }

    // ---- tail: last block of batch b performs combineU + qp ----
    __threadfence();
    if (t == 0) s_ticket = atomicAdd(&g_ctrU[b], 1u);
    __syncthreads();
    if (s_ticket != NCH - 1) return;
    if (t == 0) g_ctrU[b] = 0u;
    __threadfence();

    float* ms = sA;                   // [512] mean|sd (sA holds 1088 floats)
    float* qv = sQ;                   // [128]

    float U1 = 0.f, U2 = 0.f, U3 = 0.f;
#pragma unroll 8
    for (int c = 0; c < NCH; c++) {
        int bb = (b * NCH + c) * 3;
        U1 += g_PU[(bb + 0) * Dn + t];
        U2 += g_PU[(bb + 1) * Dn + t];
        U3 += g_PU[(bb + 2) * Dn + t];
    }
    float smr = bSum((t < NCH) ? g_Psmr[b * NCH + t] : 0.f);
    float sm2r2 = bSum((t < NCH) ? g_Ps22[b * NCH + t] : 0.f);

    {
        float g = ln_g[t], be = ln_b[t];
        float S1 = g * (U1 - smr) + (float)Ln * be;
        float S2 = g * g * (U2 - 2.0f * U3 + sm2r2) + 2.0f * g * be * (U1 - smr) + (float)Ln * be * be;
        float mean = S1 * (1.0f / Ln);
        float var = S2 * (1.0f / Ln) - mean * mean;
        float sd = sqrtf(fmaxf(var, EPS_CLIP));
        ms[t] = mean;
        ms[Dn + t] = sd;
    }
    __syncthreads();

    int w = t >> 5, lane = t & 31;
#pragma unroll
    for (int i = 0; i < 16; i++) {
        int k = w * 16 + i;
        float acc = 0.f;
        const float* wr = wq + (size_t)k * 2 * Dn;
#pragma unroll
        for (int e = 0; e < 16; e++)
            acc = fmaf(wr[e * 32 + lane], ms[e * 32 + lane], acc);
        acc = warpSum(acc);
        if (lane == 0) qv[k] = acc;
    }
    __syncthreads();

    float p = 0.f;
#pragma unroll 8
    for (int k2 = 0; k2 < DKn; k2++) p = fmaf(wk[k2 * Dn + t], qv[k2], p);
    p *= rsqrtf((float)DKn);

    float gp = ln_g[t] * p;
    g_gp[b * Dn + t] = gp;
    float cb = bSum(ln_b[t] * p);
    float gpsum = bSum(gp);
    if (t == 0) { g_Cb[b] = cb; g_Gp[b] = gpsum; }
}

// ---------------- 2. FUSED scores + chunk softmax + R-partials + (last block) combineR + finalize ----------------
__global__ void __launch_bounds__(256, 4) k_fused(const float* __restrict__ v,
                                                   const float* __restrict__ fcq_w,
                                                   const float* __restrict__ fc_w,
                                                   const float* __restrict__ fc_b,
                                                   const float* __restrict__ ln_g,
                                                   const float* __restrict__ ln_b,
                                                   float* __restrict__ out) {
    __shared__ float s_gp[Dn];
    __shared__ float s_mu[CH1], s_rs[CH1];
    __shared__ float s_c1[CH1], s_c2[CH1], s_c3[CH1];
    __shared__ float s_s[CH1];
    __shared__ float s_ml[1];
    __shared__ float sD[64 * 17];
    __shared__ unsigned int s_ticket;

    int t = threadIdx.x;                    // 256
    int b = (Bn - 1) - (blockIdx.x >> 6);   // reversed (L2 warmth after pass1)
    int ch = blockIdx.x & 63;
    int l0 = ch * CH1;
    int bc = b * NCH + ch;
    int dg = t >> 4;                        // 0..15
    int lv = t & 15;

    s_gp[t] = g_gp[b * Dn + t];
    if (t < 64) s_mu[t] = g_mu[b * Ln + l0 + t];
    else if (t < 128) s_rs[t - 64] = g_rsig[b * Ln + l0 + (t - 64)];
    __syncthreads();

    const float* vbase = v + (size_t)b * Dn * Ln + l0 + lv * 4;
    float a0 = 0.f, a1 = 0.f, a2 = 0.f, a3 = 0.f;
#pragma unroll
    for (int it = 0; it < 16; it++) {
        int d = it * 16 + dg;
        float4 x = *reinterpret_cast<const float4*>(vbase + (size_t)d * Ln);
        float g = s_gp[d];
        a0 = fmaf(x.x, g, a0);
        a1 = fmaf(x.y, g, a1);
        a2 = fmaf(x.z, g, a2);
        a3 = fmaf(x.w, g, a3);
    }
    sD[(lv * 4 + 0) * 17 + dg] = a0;
    sD[(lv * 4 + 1) * 17 + dg] = a1;
    sD[(lv * 4 + 2) * 17 + dg] = a2;
    sD[(lv * 4 + 3) * 17 + dg] = a3;
    __syncthreads();

    if (t < CH1) {
        float dot = 0.f;
#pragma unroll
        for (int g = 0; g < 16; g++) dot += sD[t * 17 + g];
        s_s[t] = s_rs[t] * (dot - s_mu[t] * g_Gp[b]) + g_Cb[b];
    }
    __syncthreads();

    if (t < 32) {
        float m = fmaxf(s_s[t], s_s[32 + t]);
        m = warpMax(m);
        if (t == 0) { s_ml[0] = m; g_Pml[bc] = m; }
    }
    __syncthreads();

    if (t < CH1) {
        float e = __expf(s_s[t] - s_ml[0]);
        float rs = s_rs[t], mu = s_mu[t];
        float c1 = e * rs;
        float c2 = c1 * rs;
        s_c1[t] = c1;
        s_c2[t] = c2;
        s_c3[t] = c2 * mu;
        float mr = mu * rs;
        sD[t] = e;
        sD[64 + t] = e * mr;
        sD[128 + t] = e * mr * mr;
    }
    __syncthreads();
    if (t < 32) {
        float a = sD[t] + sD[32 + t];
        a = warpSum(a);
        if (t == 0) g_Pse[bc] = a;
    } else if (t < 64) {
        int u = t - 32;
        float a = sD[64 + u] + sD[96 + u];
        a = warpSum(a);
        if (u == 0) g_Pa[bc] = a;
    } else if (t < 96) {
        int u = t - 64;
        float a = sD[128 + u] + sD[160 + u];
        a = warpSum(a);
        if (u == 0) g_Pm2[bc] = a;
    }
    __syncthreads();

    float c10 = s_c1[lv * 4 + 0], c11 = s_c1[lv * 4 + 1], c12 = s_c1[lv * 4 + 2], c13 = s_c1[lv * 4 + 3];
    float c20 = s_c2[lv * 4 + 0], c21 = s_c2[lv * 4 + 1], c22 = s_c2[lv * 4 + 2], c23 = s_c2[lv * 4 + 3];
    float c30 = s_c3[lv * 4 + 0], c31 = s_c3[lv * 4 + 1], c32 = s_c3[lv * 4 + 2], c33 = s_c3[lv * 4 + 3];

#pragma unroll
    for (int it = 0; it < 16; it++) {
        int d = it * 16 + dg;
        float4 xx = *reinterpret_cast<const float4*>(vbase + (size_t)d * Ln);
        float r1 = fmaf(xx.x, c10, fmaf(xx.y, c11, fmaf(xx.z, c12, xx.w * c13)));
        float r2 = fmaf(xx.x * xx.x, c20, fmaf(xx.y * xx.y, c21,
                   fmaf(xx.z * xx.z, c22, (xx.w * xx.w) * c23)));
        float r3 = fmaf(xx.x, c30, fmaf(xx.y, c31, fmaf(xx.z, c32, xx.w * c33)));
#pragma unroll
        for (int o = 8; o; o >>= 1) {
            r1 += __shfl_down_sync(0xffffffffu, r1, o);
            r2 += __shfl_down_sync(0xffffffffu, r2, o);
            r3 += __shfl_down_sync(0xffffffffu, r3, o);
        }
        if (lv == 0) {
            g_PR[(bc * 3 + 0) * Dn + d] = r1;
            g_PR[(bc * 3 + 1) * Dn + d] = r2;
            g_PR[(bc * 3 + 2) * Dn + d] = r3;
        }
    }

    // ---- tail: last block of batch b performs combineR + finalize ----
    __threadfence();
    if (t == 0) s_ticket = atomicAdd(&g_ctrR[b], 1u);
    __syncthreads();
    if (s_ticket != NCH - 1) return;
    if (t == 0) g_ctrR[b] = 0u;
    __threadfence();

    int w = t >> 5, lane = t & 31;
    if (t < 32) {
        float m = fmaxf(g_Pml[b * NCH + t], g_Pml[b * NCH + 32 + t]);
        m = warpMax(m);
        if (t == 0) s_ml[0] = m;
    }
    __syncthreads();
    float M = s_ml[0];
    if (t < NCH) s_c1[t] = __expf(g_Pml[b * NCH + t] - M);   // scale[64]
    __syncthreads();

    float R1 = 0.f, R2 = 0.f, R3 = 0.f;
#pragma unroll 8
    for (int c = 0; c < NCH; c++) {
        int bb = (b * NCH + c) * 3;
        float sc = s_c1[c];
        R1 = fmaf(g_PR[(bb + 0) * Dn + t], sc, R1);
        R2 = fmaf(g_PR[(bb + 1) * Dn + t], sc, R2);
        R3 = fmaf(g_PR[(bb + 2) * Dn + t], sc, R3);
    }
    float SE = bSum((t < NCH) ? g_Pse[b * NCH + t] * s_c1[t] : 0.f);
    float Asum = bSum((t < NCH) ? g_Pa[b * NCH + t] * s_c1[t] : 0.f);
    float M2sum = bSum((t < NCH) ? g_Pm2[b * NCH + t] * s_c1[t] : 0.f);
    float inv = 1.0f / SE;
    float A = Asum * inv, M2 = M2sum * inv;

    float* am = sD;          // [256]
    float* as = sD + Dn;     // [256]
    {
        float g = ln_g[t], be = ln_b[t];
        R1 *= inv; R2 *= inv; R3 *= inv;
        float mean = g * (R1 - A) + be;
        float E2 = g * g * (R2 - 2.0f * R3 + M2) + 2.0f * g * be * (R1 - A) + be * be;
        float var = E2 - mean * mean;
        am[t] = mean;
        as[t] = sqrtf(fmaxf(var, EPS_CLIP));
    }
    __syncthreads();

#pragma unroll
    for (int i = 0; i < 32; i++) {
        int o = w * 32 + i;
        const float* wr = fcq_w + (size_t)o * Dn;
        float c = 0.f;
#pragma unroll
        for (int e = 0; e < 8; e++)
            c = fmaf(wr[e * 32 + lane], am[e * 32 + lane], c);
        c = warpSum(c);

        const float* fr = fc_w + (size_t)o * 2 * Dn;
        float sk = 0.f;
#pragma unroll
        for (int e = 0; e < 8; e++) {
            sk = fmaf(fr[e * 32 + lane], am[e * 32 + lane], sk);
            sk = fmaf(fr[Dn + e * 32 + lane], as[e * 32 + lane], sk);
        }
        sk = warpSum(sk);

        if (lane == 0) {
            g_corr[b * Dn + o] = c;
            out[(size_t)Bn * Ln * Dn + b * Dn + o] = sk + fc_b[o];
        }
    }
}

// ---------------- 3. out1[b,l,o] = v[b,o,l] + corr[b,o] ----------------
__global__ void k_out(const float* __restrict__ v, float* __restrict__ out) {
    __shared__ float tile[32 * 129];
    int b = (Bn - 1) - blockIdx.z;
    int l0 = blockIdx.x * 128;
    int o0 = blockIdx.y * 32;
    int tid = threadIdx.x;          // 256
    int w = tid >> 5, lane = tid & 31;

#pragma unroll
    for (int i = 0; i < 4; i++) {
        int ol = w + 8 * i;
        int o = o0 + ol;
        float c = g_corr[b * Dn + o];
        const float4* vr = reinterpret_cast<const float4*>(v + ((size_t)(b * Dn + o)) * Ln + l0);
        float4 x = __ldcs(vr + lane);
        tile[ol * 129 + lane * 4 + 0] = x.x + c;
        tile[ol * 129 + lane * 4 + 1] = x.y + c;
        tile[ol * 129 + lane * 4 + 2] = x.z + c;
        tile[ol * 129 + lane * 4 + 3] = x.w + c;
    }
    __syncthreads();

    int o4 = tid & 7;
    int lq = tid >> 3;
#pragma unroll
    for (int i = 0; i < 4; i++) {
        int l = i * 32 + lq;
        float4 y;
        y.x = tile[(o4 * 4 + 0) * 129 + l];
        y.y = tile[(o4 * 4 + 1) * 129 + l];
        y.z = tile[(o4 * 4 + 2) * 129 + l];
        y.w = tile[(o4 * 4 + 3) * 129 + l];
        __stcs(reinterpret_cast<float4*>(out + ((size_t)b * Ln + l0 + l) * Dn + o0 + o4 * 4), y);
    }
}

// ---------------- launcher: 3-kernel chain ----------------
extern "C" void kernel_launch(void* const* d_in, const int* in_sizes, int n_in,
                              void* d_out, int out_size) {
    const float* v     = (const float*)d_in[0];
    const float* ln_g  = (const float*)d_in[1];
    const float* ln_b  = (const float*)d_in[2];
    const float* wk    = (const float*)d_in[3];
    const float* wq    = (const float*)d_in[4];
    const float* fcq_w = (const float*)d_in[5];
    const float* fc_w  = (const float*)d_in[6];
    const float* fc_b  = (const float*)d_in[7];
    float* out = (float*)d_out;

    k_pass1<<<Bn * NCH, 256>>>(v, wk, wq, ln_g, ln_b);
    k_fused<<<Bn * NCH, 256>>>(v, fcq_w, fc_w, fc_b, ln_g, ln_b, out);
    k_out<<<dim3(Ln / 128, Dn / 32, Bn), 256>>>(v, out);
}

// round 17
// speedup vs baseline: 1.0238x; 1.0238x over previous
#include <cuda_runtime.h>
#include <cfloat>
#include <math.h>

#define Bn 64
#define Dn 256
#define Ln 4096
#define DKn 128
#define LN_EPS 1e-6f
#define EPS_CLIP 1e-10f

#define CH1 64                 // l-chunk per block
#define NCH (Ln / CH1)         // 64 chunks per batch

#define GP1 (Bn * NCH)         // 4096 pass1 blocks
#define GF  (Bn * NCH)         // 4096 fused blocks
#define GO  (16 * 8 * Bn)      // 8192 paired-out blocks (2 x 128l per block)

// ---------------- scratch (static device globals; no allocation) ----------------
__device__ float g_mu[Bn * Ln];
__device__ float g_rsig[Bn * Ln];
__device__ float g_PU[Bn * NCH * 3 * Dn];
__device__ float g_PR[Bn * NCH * 3 * Dn];
__device__ float g_Psmr[Bn * NCH];
__device__ float g_Ps22[Bn * NCH];
__device__ float g_Pml[Bn * NCH];
__device__ float g_Pse[Bn * NCH];
__device__ float g_Pa[Bn * NCH];
__device__ float g_Pm2[Bn * NCH];
__device__ float g_gp[Bn * Dn];
__device__ float g_corr[Bn * Dn];
__device__ float g_Cb[Bn], g_Gp[Bn];
__device__ unsigned int g_ctrU[Bn];     // pass1 ticket; winner resets
__device__ unsigned int g_ctrR[Bn];     // fused ticket; winner resets
__device__ unsigned int g_qp_done[Bn];  // published by pass1 tail; last fused consumer resets
__device__ unsigned int g_fin_done[Bn]; // published by fused tail; last out consumer resets
__device__ unsigned int g_qpObs[Bn];
__device__ unsigned int g_finObs[Bn];

// ---------------- reduction helpers ----------------
__device__ __forceinline__ float warpSum(float v) {
#pragma unroll
    for (int o = 16; o; o >>= 1) v += __shfl_xor_sync(0xffffffffu, v, o);
    return v;
}
__device__ __forceinline__ float warpMax(float v) {
#pragma unroll
    for (int o = 16; o; o >>= 1) v = fmaxf(v, __shfl_xor_sync(0xffffffffu, v, o));
    return v;
}
__device__ __forceinline__ float bSum(float v) {
    __shared__ float sh[32];
    int lane = threadIdx.x & 31, w = threadIdx.x >> 5;
    int nw = (blockDim.x + 31) >> 5;
    v = warpSum(v);
    if (lane == 0) sh[w] = v;
    __syncthreads();
    if (w == 0) {
        float x = (lane < nw) ? sh[lane] : 0.0f;
        x = warpSum(x);
        if (lane == 0) sh[0] = x;
    }
    __syncthreads();
    float r = sh[0];
    __syncthreads();
    return r;
}

// =====================================================================
// single mega-kernel: role by blockIdx
//   [0, GP1)            pass1: LN stats + U partials (+tail: combineU + qp, publish qp_done)
//   [GP1, GP1+GF)       fused: scores + chunk softmax + R partials (spin qp_done)
//                              (+tail: combineR + finalize, publish fin_done)
//   [GP1+GF, +GO)       out:   transpose + corr add (spin fin_done)
// =====================================================================
__global__ void __launch_bounds__(512, 2) k_mega(const float* __restrict__ v,
                                                 const float* __restrict__ wk,
                                                 const float* __restrict__ wq,
                                                 const float* __restrict__ fcq_w,
                                                 const float* __restrict__ fc_w,
                                                 const float* __restrict__ fc_b,
                                                 const float* __restrict__ ln_g,
                                                 const float* __restrict__ ln_b,
                                                 float* __restrict__ out) {
    __shared__ float sraw[2 * 32 * 129];      // 8256 floats = 33 KB union for all roles
    __shared__ unsigned int s_ticket;

    int t = threadIdx.x;                      // 512
    int idx = blockIdx.x;

    // =================== ROLE 1: pass1 ===================
    if (idx < GP1) {
        float* s_mu = sraw;                   // 64
        float* s_rs = sraw + 64;              // 64
        float* s_mr = sraw + 128;             // 64
        float* s_m2 = sraw + 192;             // 64
        float* sA   = sraw + 256;             // 2112
        float* sQ   = sraw + 2368;            // 2112

        int b = idx >> 6;
        int ch = idx & 63;
        int l0 = ch * CH1;
        int bc = idx;
        int dg = t >> 4;                      // 0..31
        int lv = t & 15;

        const float* vbase = v + (size_t)b * Dn * Ln + l0 + lv * 4;
        float cs0 = 0.f, cs1 = 0.f, cs2 = 0.f, cs3 = 0.f;
        float cq0 = 0.f, cq1 = 0.f, cq2 = 0.f, cq3 = 0.f;
#pragma unroll
        for (int it = 0; it < 8; it++) {
            int d = it * 32 + dg;
            float4 x = *reinterpret_cast<const float4*>(vbase + (size_t)d * Ln);
            cs0 += x.x; cs1 += x.y; cs2 += x.z; cs3 += x.w;
            cq0 = fmaf(x.x, x.x, cq0);
            cq1 = fmaf(x.y, x.y, cq1);
            cq2 = fmaf(x.z, x.z, cq2);
            cq3 = fmaf(x.w, x.w, cq3);
        }
        sA[(lv * 4 + 0) * 33 + dg] = cs0;
        sA[(lv * 4 + 1) * 33 + dg] = cs1;
        sA[(lv * 4 + 2) * 33 + dg] = cs2;
        sA[(lv * 4 + 3) * 33 + dg] = cs3;
        sQ[(lv * 4 + 0) * 33 + dg] = cq0;
        sQ[(lv * 4 + 1) * 33 + dg] = cq1;
        sQ[(lv * 4 + 2) * 33 + dg] = cq2;
        sQ[(lv * 4 + 3) * 33 + dg] = cq3;
        __syncthreads();

        if (t < CH1) {
            float ss = 0.f, qq = 0.f;
#pragma unroll
            for (int g = 0; g < 32; g++) {
                ss += sA[t * 33 + g];
                qq += sQ[t * 33 + g];
            }
            float mu = ss * (1.0f / Dn);
            float var = qq * (1.0f / Dn) - mu * mu;
            float rs = rsqrtf(var + LN_EPS);
            s_mu[t] = mu;
            s_rs[t] = rs;
            g_mu[b * Ln + l0 + t] = mu;
            g_rsig[b * Ln + l0 + t] = rs;
            float mr = mu * rs;
            s_mr[t] = mr;
            s_m2[t] = mr * mr;
        }
        __syncthreads();

        if (t < 32) {
            float a = s_mr[t] + s_mr[32 + t];
            a = warpSum(a);
            if (t == 0) g_Psmr[bc] = a;
        } else if (t < 64) {
            int u = t - 32;
            float a = s_m2[u] + s_m2[32 + u];
            a = warpSum(a);
            if (u == 0) g_Ps22[bc] = a;
        }

        float r0 = s_rs[lv * 4 + 0], r1 = s_rs[lv * 4 + 1], r2 = s_rs[lv * 4 + 2], r3 = s_rs[lv * 4 + 3];
        float am0 = s_mu[lv * 4 + 0] * r0 * r0;
        float am1 = s_mu[lv * 4 + 1] * r1 * r1;
        float am2 = s_mu[lv * 4 + 2] * r2 * r2;
        float am3 = s_mu[lv * 4 + 3] * r3 * r3;

#pragma unroll
        for (int it = 0; it < 8; it++) {
            int d = it * 32 + dg;
            float4 xx = *reinterpret_cast<const float4*>(vbase + (size_t)d * Ln);
            float xr0 = xx.x * r0, xr1 = xx.y * r1, xr2 = xx.z * r2, xr3 = xx.w * r3;
            float u1 = (xr0 + xr1) + (xr2 + xr3);
            float u2 = fmaf(xr0, xr0, fmaf(xr1, xr1, fmaf(xr2, xr2, xr3 * xr3)));
            float u3 = fmaf(xx.x, am0, fmaf(xx.y, am1, fmaf(xx.z, am2, xx.w * am3)));
#pragma unroll
            for (int o = 8; o; o >>= 1) {
                u1 += __shfl_down_sync(0xffffffffu, u1, o);
                u2 += __shfl_down_sync(0xffffffffu, u2, o);
                u3 += __shfl_down_sync(0xffffffffu, u3, o);
            }
            if (lv == 0) {
                g_PU[(bc * 3 + 0) * Dn + d] = u1;
                g_PU[(bc * 3 + 1) * Dn + d] = u2;
                g_PU[(bc * 3 + 2) * Dn + d] = u3;
            }
        }

        // ---- tail: last block of batch b -> combineU + qp, publish qp_done ----
        __threadfence();
        if (t == 0) s_ticket = atomicAdd(&g_ctrU[b], 1u);
        __syncthreads();
        if (s_ticket != NCH - 1) return;
        if (t == 0) g_ctrU[b] = 0u;
        __threadfence();

        float* ms = sA;                       // [512]
        float* qv = sQ;                       // [128]

        float U1 = 0.f, U2 = 0.f, U3 = 0.f;
        if (t < Dn) {
#pragma unroll 8
            for (int c = 0; c < NCH; c++) {
                int bb = (b * NCH + c) * 3;
                U1 += g_PU[(bb + 0) * Dn + t];
                U2 += g_PU[(bb + 1) * Dn + t];
                U3 += g_PU[(bb + 2) * Dn + t];
            }
        }
        float smr = bSum((t >= 256 && t < 320) ? g_Psmr[b * NCH + (t - 256)] : 0.f);
        float sm2r2 = bSum((t >= 320 && t < 384) ? g_Ps22[b * NCH + (t - 320)] : 0.f);

        if (t < Dn) {
            float g = ln_g[t], be = ln_b[t];
            float S1 = g * (U1 - smr) + (float)Ln * be;
            float S2 = g * g * (U2 - 2.0f * U3 + sm2r2) + 2.0f * g * be * (U1 - smr) + (float)Ln * be * be;
            float mean = S1 * (1.0f / Ln);
            float var = S2 * (1.0f / Ln) - mean * mean;
            float sd = sqrtf(fmaxf(var, EPS_CLIP));
            ms[t] = mean;
            ms[Dn + t] = sd;
        }
        __syncthreads();

        int w = t >> 5, lane = t & 31;
        if (t < Dn) {
#pragma unroll
            for (int i = 0; i < 16; i++) {
                int k = w * 16 + i;
                float acc = 0.f;
                const float* wr = wq + (size_t)k * 2 * Dn;
#pragma unroll
                for (int e = 0; e < 16; e++)
                    acc = fmaf(wr[e * 32 + lane], ms[e * 32 + lane], acc);
                acc = warpSum(acc);
                if (lane == 0) qv[k] = acc;
            }
        }
        __syncthreads();

        float p = 0.f, gp = 0.f, cbv = 0.f;
        if (t < Dn) {
#pragma unroll 8
            for (int k2 = 0; k2 < DKn; k2++) p = fmaf(wk[k2 * Dn + t], qv[k2], p);
            p *= rsqrtf((float)DKn);
            gp = ln_g[t] * p;
            g_gp[b * Dn + t] = gp;
            cbv = ln_b[t] * p;
        }
        float cb = bSum(cbv);
        float gpsum = bSum(gp);
        if (t == 0) {
            g_Cb[b] = cb;
            g_Gp[b] = gpsum;
            __threadfence();
            atomicExch(&g_qp_done[b], 1u);
        }
        return;
    }

    // =================== ROLE 2: fused ===================
    if (idx < GP1 + GF) {
        int f = idx - GP1;
        int b = f >> 6;                       // ascending, aligned with pass1
        int ch = f & 63;
        int l0 = ch * CH1;
        int bc = b * NCH + ch;
        int dg = t >> 4;
        int lv = t & 15;

        float* s_gp = sraw;                   // 256
        float* s_mu = sraw + 256;             // 64
        float* s_rs = sraw + 320;             // 64
        float* s_c1 = sraw + 384;             // 64
        float* s_c2 = sraw + 448;             // 64
        float* s_c3 = sraw + 512;             // 64
        float* s_s  = sraw + 576;             // 64
        float* s_ml = sraw + 640;             // 1
        float* sA   = sraw + 656;             // 2112

        // wait for this batch's qp results
        if (t == 0) {
            while (atomicAdd(&g_qp_done[b], 0u) == 0u) __nanosleep(200);
        }
        __syncthreads();

        if (t < Dn) s_gp[t] = g_gp[b * Dn + t];
        if (t >= 256 && t < 320) s_mu[t - 256] = g_mu[b * Ln + l0 + (t - 256)];
        if (t >= 320 && t < 384) s_rs[t - 320] = g_rsig[b * Ln + l0 + (t - 320)];
        __syncthreads();

        const float* vbase = v + (size_t)b * Dn * Ln + l0 + lv * 4;
        float a0 = 0.f, a1 = 0.f, a2 = 0.f, a3 = 0.f;
#pragma unroll
        for (int it = 0; it < 8; it++) {
            int d = it * 32 + dg;
            float4 x = *reinterpret_cast<const float4*>(vbase + (size_t)d * Ln);
            float g = s_gp[d];
            a0 = fmaf(x.x, g, a0);
            a1 = fmaf(x.y, g, a1);
            a2 = fmaf(x.z, g, a2);
            a3 = fmaf(x.w, g, a3);
        }
        sA[(lv * 4 + 0) * 33 + dg] = a0;
        sA[(lv * 4 + 1) * 33 + dg] = a1;
        sA[(lv * 4 + 2) * 33 + dg] = a2;
        sA[(lv * 4 + 3) * 33 + dg] = a3;
        __syncthreads();

        if (t < CH1) {
            float dot = 0.f;
#pragma unroll
            for (int g = 0; g < 32; g++) dot += sA[t * 33 + g];
            s_s[t] = s_rs[t] * (dot - s_mu[t] * g_Gp[b]) + g_Cb[b];
        }
        __syncthreads();

        if (t < 32) {
            float m = fmaxf(s_s[t], s_s[32 + t]);
            m = warpMax(m);
            if (t == 0) { s_ml[0] = m; g_Pml[bc] = m; }
        }
        __syncthreads();

        if (t < CH1) {
            float e = __expf(s_s[t] - s_ml[0]);
            float rs = s_rs[t], mu = s_mu[t];
            float c1 = e * rs;
            float c2 = c1 * rs;
            s_c1[t] = c1;
            s_c2[t] = c2;
            s_c3[t] = c2 * mu;
            float mr = mu * rs;
            sA[t] = e;
            sA[64 + t] = e * mr;
            sA[128 + t] = e * mr * mr;
        }
        __syncthreads();
        if (t < 32) {
            float a = sA[t] + sA[32 + t];
            a = warpSum(a);
            if (t == 0) g_Pse[bc] = a;
        } else if (t < 64) {
            int u = t - 32;
            float a = sA[64 + u] + sA[96 + u];
            a = warpSum(a);
            if (u == 0) g_Pa[bc] = a;
        } else if (t < 96) {
            int u = t - 64;
            float a = sA[128 + u] + sA[160 + u];
            a = warpSum(a);
            if (u == 0) g_Pm2[bc] = a;
        }
        __syncthreads();

        float c10 = s_c1[lv * 4 + 0], c11 = s_c1[lv * 4 + 1], c12 = s_c1[lv * 4 + 2], c13 = s_c1[lv * 4 + 3];
        float c20 = s_c2[lv * 4 + 0], c21 = s_c2[lv * 4 + 1], c22 = s_c2[lv * 4 + 2], c23 = s_c2[lv * 4 + 3];
        float c30 = s_c3[lv * 4 + 0], c31 = s_c3[lv * 4 + 1], c32 = s_c3[lv * 4 + 2], c33 = s_c3[lv * 4 + 3];

#pragma unroll
        for (int it = 0; it < 8; it++) {
            int d = it * 32 + dg;
            float4 xx = *reinterpret_cast<const float4*>(vbase + (size_t)d * Ln);
            float r1 = fmaf(xx.x, c10, fmaf(xx.y, c11, fmaf(xx.z, c12, xx.w * c13)));
            float r2 = fmaf(xx.x * xx.x, c20, fmaf(xx.y * xx.y, c21,
                       fmaf(xx.z * xx.z, c22, (xx.w * xx.w) * c23)));
            float r3 = fmaf(xx.x, c30, fmaf(xx.y, c31, fmaf(xx.z, c32, xx.w * c33)));
#pragma unroll
            for (int o = 8; o; o >>= 1) {
                r1 += __shfl_down_sync(0xffffffffu, r1, o);
                r2 += __shfl_down_sync(0xffffffffu, r2, o);
                r3 += __shfl_down_sync(0xffffffffu, r3, o);
            }
            if (lv == 0) {
                g_PR[(bc * 3 + 0) * Dn + d] = r1;
                g_PR[(bc * 3 + 1) * Dn + d] = r2;
                g_PR[(bc * 3 + 2) * Dn + d] = r3;
            }
        }

        // consumer bookkeeping for qp_done reset (after use)
        if (t == 0) {
            if (atomicAdd(&g_qpObs[b], 1u) == NCH - 1u) {
                atomicExch(&g_qp_done[b], 0u);
                atomicExch(&g_qpObs[b], 0u);
            }
        }

        // ---- tail: last block of batch b -> combineR + finalize, publish fin_done ----
        __threadfence();
        if (t == 0) s_ticket = atomicAdd(&g_ctrR[b], 1u);
        __syncthreads();
        if (s_ticket != NCH - 1) return;
        if (t == 0) g_ctrR[b] = 0u;
        __threadfence();

        int w = t >> 5, lane = t & 31;
        if (t < 32) {
            float m = fmaxf(g_Pml[b * NCH + t], g_Pml[b * NCH + 32 + t]);
            m = warpMax(m);
            if (t == 0) s_ml[0] = m;
        }
        __syncthreads();
        float M = s_ml[0];
        if (t < NCH) s_c1[t] = __expf(g_Pml[b * NCH + t] - M);
        __syncthreads();

        float R1 = 0.f, R2 = 0.f, R3 = 0.f;
        if (t < Dn) {
#pragma unroll 8
            for (int c = 0; c < NCH; c++) {
                int bb = (b * NCH + c) * 3;
                float sc = s_c1[c];
                R1 = fmaf(g_PR[(bb + 0) * Dn + t], sc, R1);
                R2 = fmaf(g_PR[(bb + 1) * Dn + t], sc, R2);
                R3 = fmaf(g_PR[(bb + 2) * Dn + t], sc, R3);
            }
        }
        float SE = bSum((t >= 256 && t < 320) ? g_Pse[b * NCH + (t - 256)] * s_c1[t - 256] : 0.f);
        float Asum = bSum((t >= 320 && t < 384) ? g_Pa[b * NCH + (t - 320)] * s_c1[t - 320] : 0.f);
        float M2sum = bSum((t >= 384 && t < 448) ? g_Pm2[b * NCH + (t - 384)] * s_c1[t - 384] : 0.f);
        float inv = 1.0f / SE;
        float A = Asum * inv, M2 = M2sum * inv;

        float* am = sA;
        float* as = sA + Dn;
        if (t < Dn) {
            float g = ln_g[t], be = ln_b[t];
            R1 *= inv; R2 *= inv; R3 *= inv;
            float mean = g * (R1 - A) + be;
            float E2 = g * g * (R2 - 2.0f * R3 + M2) + 2.0f * g * be * (R1 - A) + be * be;
            float var = E2 - mean * mean;
            am[t] = mean;
            as[t] = sqrtf(fmaxf(var, EPS_CLIP));
        }
        __syncthreads();

        if (t < Dn) {
#pragma unroll
            for (int i = 0; i < 32; i++) {
                int o = w * 32 + i;
                const float* wr = fcq_w + (size_t)o * Dn;
                float c = 0.f;
#pragma unroll
                for (int e = 0; e < 8; e++)
                    c = fmaf(wr[e * 32 + lane], am[e * 32 + lane], c);
                c = warpSum(c);

                const float* fr = fc_w + (size_t)o * 2 * Dn;
                float sk = 0.f;
#pragma unroll
                for (int e = 0; e < 8; e++) {
                    sk = fmaf(fr[e * 32 + lane], am[e * 32 + lane], sk);
                    sk = fmaf(fr[Dn + e * 32 + lane], as[e * 32 + lane], sk);
                }
                sk = warpSum(sk);

                if (lane == 0) {
                    g_corr[b * Dn + o] = c;
                    out[(size_t)Bn * Ln * Dn + b * Dn + o] = sk + fc_b[o];
                }
            }
        }
        __threadfence();
        __syncthreads();
        if (t == 0) atomicExch(&g_fin_done[b], 1u);
        return;
    }

    // =================== ROLE 3: out (paired tiles, 512 threads) ===================
    {
        int o = idx - GP1 - GF;               // 0..GO-1
        int b = o >> 7;                       // 128 blocks per batch
        int rem = o & 127;
        int xp = rem & 15;                    // 16 l-pairs
        int yo = rem >> 4;                    // 0..7
        int sub = t >> 8;                     // 0/1: which 128-l tile
        int tid = t & 255;
        int l0 = (xp * 2 + sub) * 128;
        int o0 = yo * 32;
        float* tile = sraw + sub * (32 * 129);

        if (t == 0) {
            while (atomicAdd(&g_fin_done[b], 0u) == 0u) __nanosleep(200);
        }
        __syncthreads();

        int w = tid >> 5, lane = tid & 31;
#pragma unroll
        for (int i = 0; i < 4; i++) {
            int ol = w + 8 * i;
            int oo = o0 + ol;
            float c = g_corr[b * Dn + oo];
            const float4* vr = reinterpret_cast<const float4*>(v + ((size_t)(b * Dn + oo)) * Ln + l0);
            float4 x = __ldcs(vr + lane);
            tile[ol * 129 + lane * 4 + 0] = x.x + c;
            tile[ol * 129 + lane * 4 + 1] = x.y + c;
            tile[ol * 129 + lane * 4 + 2] = x.z + c;
            tile[ol * 129 + lane * 4 + 3] = x.w + c;
        }
        __syncthreads();

        int o4 = tid & 7;
        int lq = tid >> 3;
#pragma unroll
        for (int i = 0; i < 4; i++) {
            int l = i * 32 + lq;
            float4 y;
            y.x = tile[(o4 * 4 + 0) * 129 + l];
            y.y = tile[(o4 * 4 + 1) * 129 + l];
            y.z = tile[(o4 * 4 + 2) * 129 + l];
            y.w = tile[(o4 * 4 + 3) * 129 + l];
            __stcs(reinterpret_cast<float4*>(out + ((size_t)b * Ln + l0 + l) * Dn + o0 + o4 * 4), y);
        }

        if (t == 0) {
            if (atomicAdd(&g_finObs[b], 1u) == 127u) {
                atomicExch(&g_fin_done[b], 0u);
                atomicExch(&g_finObs[b], 0u);
            }
        }
    }
}

// ---------------- launcher: ONE kernel ----------------
extern "C" void kernel_launch(void* const* d_in, const int* in_sizes, int n_in,
                              void* d_out, int out_size) {
    const float* v     = (const float*)d_in[0];
    const float* ln_g  = (const float*)d_in[1];
    const float* ln_b  = (const float*)d_in[2];
    const float* wk    = (const float*)d_in[3];
    const float* wq    = (const float*)d_in[4];
    const float* fcq_w = (const float*)d_in[5];
    const float* fc_w  = (const float*)d_in[6];
    const float* fc_b  = (const float*)d_in[7];
    float* out = (float*)d_out;

    k_mega<<<GP1 + GF + GO, 512>>>(v, wk, wq, fcq_w, fc_w, fc_b, ln_g, ln_b, out);
}